// round 2
// baseline (speedup 1.0000x reference)
#include <cuda_runtime.h>
#include <cstdint>

#define D_MODEL 2048
#define NUM_EXPERTS 64
#define M_TILE 64
#define KC 16
#define NTHREADS 128
#define LOGIT_STRIDE 66

// smem stage layout (floats):
//  xs: [KC][64]   (k-major, rows contiguous)            1024 floats/stage
//  ws: [KC][128]  (k-major, experts DUPLICATED: [2e],[2e+1] = w[e][k])  2048 floats/stage
#define XSTAGE (KC * 64)
#define WSTAGE (KC * 128)
#define SMEM_FLOATS (2 * XSTAGE + 2 * WSTAGE)   // 6144 floats = 24576 B (>= 64*66 logits)

__device__ __forceinline__ unsigned long long dup2(float v) {
    unsigned long long r;
    unsigned u = __float_as_uint(v);
    asm("mov.b64 %0, {%1, %1};" : "=l"(r) : "r"(u));
    return r;
}
__device__ __forceinline__ void ffma2(unsigned long long& acc, unsigned long long a, unsigned long long b) {
    asm("fma.rn.f32x2 %0, %1, %2, %0;" : "+l"(acc) : "l"(a), "l"(b));
}
__device__ __forceinline__ float2 unpack2(unsigned long long v) {
    unsigned lo, hi;
    asm("mov.b64 {%0, %1}, %2;" : "=r"(lo), "=r"(hi) : "l"(v));
    return make_float2(__uint_as_float(lo), __uint_as_float(hi));
}

__global__ void __launch_bounds__(NTHREADS, 4) router_kernel(
    const float* __restrict__ x,
    const float* __restrict__ w,
    const float* __restrict__ bias,
    float* __restrict__ out,
    int n_rows)
{
    __shared__ float smem[SMEM_FLOATS];
    float* xs0 = smem;
    float* xs1 = smem + XSTAGE;
    float* ws0 = smem + 2 * XSTAGE;
    float* ws1 = smem + 2 * XSTAGE + WSTAGE;

    const int tid = threadIdx.x;
    const int tr = tid & 15;    // row-group: rows 4*tr .. 4*tr+3
    const int ec = tid >> 4;    // expert-group: experts 8*ec .. 8*ec+7
    const int lr = tid & 63;    // loader: row / expert index
    const int lk = tid >> 6;    // loader: 0..1 (k sub-chunk)
    const long long row0 = (long long)blockIdx.x * M_TILE;

    // acc[rp][m]: f32x2 over rows (4tr+2rp, 4tr+2rp+1), expert 8ec+m
    unsigned long long acc[2][8];
#pragma unroll
    for (int rp = 0; rp < 2; rp++)
#pragma unroll
        for (int m = 0; m < 8; m++) acc[rp][m] = 0ull;

    float4 xv[2];
    float4 wv[2];

    const float* xbase = x + row0 * D_MODEL;

    auto loadg = [&](int t) {
        const float* xp = xbase + (long long)lr * D_MODEL + t * KC + 4 * lk;
        xv[0] = *reinterpret_cast<const float4*>(xp);
        xv[1] = *reinterpret_cast<const float4*>(xp + 8);
        const float* wp = w + (long long)lr * D_MODEL + t * KC + 4 * lk;
        wv[0] = *reinterpret_cast<const float4*>(wp);
        wv[1] = *reinterpret_cast<const float4*>(wp + 8);
    };

    auto stores = [&](float* xb, float* wb) {
        float xf0[4] = {xv[0].x, xv[0].y, xv[0].z, xv[0].w};
        float xf1[4] = {xv[1].x, xv[1].y, xv[1].z, xv[1].w};
        float wf0[4] = {wv[0].x, wv[0].y, wv[0].z, wv[0].w};
        float wf1[4] = {wv[1].x, wv[1].y, wv[1].z, wv[1].w};
#pragma unroll
        for (int i = 0; i < 4; i++) {
            xb[(4 * lk + i) * 64 + lr]     = xf0[i];
            xb[(4 * lk + 8 + i) * 64 + lr] = xf1[i];
            *reinterpret_cast<unsigned long long*>(wb + (4 * lk + i) * 128 + 2 * lr)     = dup2(wf0[i]);
            *reinterpret_cast<unsigned long long*>(wb + (4 * lk + 8 + i) * 128 + 2 * lr) = dup2(wf1[i]);
        }
    };

    auto compute = [&](const float* xb, const float* wb) {
#pragma unroll
        for (int k = 0; k < KC; k++) {
            ulonglong2 xq = *reinterpret_cast<const ulonglong2*>(xb + k * 64 + 4 * tr);
#pragma unroll
            for (int j = 0; j < 4; j++) {
                ulonglong2 wq = *reinterpret_cast<const ulonglong2*>(wb + k * 128 + 16 * ec + 4 * j);
                ffma2(acc[0][2 * j],     xq.x, wq.x);
                ffma2(acc[0][2 * j + 1], xq.x, wq.y);
                ffma2(acc[1][2 * j],     xq.y, wq.x);
                ffma2(acc[1][2 * j + 1], xq.y, wq.y);
            }
        }
    };

    const int T = D_MODEL / KC;  // 128

    loadg(0);
    stores(xs0, ws0);
    __syncthreads();

#pragma unroll 1
    for (int t = 0; t < T - 1; ++t) {
        loadg(t + 1);
        if (t & 1) compute(xs1, ws1);
        else       compute(xs0, ws0);
        if ((t + 1) & 1) stores(xs1, ws1);
        else             stores(xs0, ws0);
        __syncthreads();
    }
    if ((T - 1) & 1) compute(xs1, ws1);
    else             compute(xs0, ws0);

    __syncthreads();  // tiles dead; smem becomes logits buffer

    // Scatter logits [64][64] (stride 66)
    float* logits = smem;
#pragma unroll
    for (int rp = 0; rp < 2; rp++) {
#pragma unroll
        for (int m = 0; m < 8; m++) {
            float2 v = unpack2(acc[rp][m]);
            int e = 8 * ec + m;
            logits[(4 * tr + 2 * rp) * LOGIT_STRIDE + e]     = v.x;
            logits[(4 * tr + 2 * rp + 1) * LOGIT_STRIDE + e] = v.y;
        }
    }
    __syncthreads();

    // One row per thread (tid < 64): softmax + top-2 + renormalize
    if (tid < M_TILE) {
        const int r = tid;
        const float* lrow = logits + r * LOGIT_STRIDE;
        float v0 = -3.0e38f, v1 = -3.0e38f;
        int i0 = 0, i1 = 0;
#pragma unroll
        for (int e = 0; e < NUM_EXPERTS; e++) {
            float l = lrow[e] + __ldg(&bias[e]);
            if (l > v0) { v1 = v0; i1 = i0; v0 = l; i0 = e; }
            else if (l > v1) { v1 = l; i1 = e; }
        }
        float Z = 0.0f;
#pragma unroll
        for (int e = 0; e < NUM_EXPERTS; e++) {
            float l = lrow[e] + __ldg(&bias[e]);
            Z += __expf(l - v0);
        }
        float q0 = 1.0f / Z;
        float q1 = __expf(v1 - v0) / Z;
        float s = q0 + q1 + 1e-8f;
        long long gr = row0 + r;
        out[gr * 2 + 0] = q0 / s;
        out[gr * 2 + 1] = q1 / s;
        float* ido = out + (long long)n_rows * 2;
        ido[gr * 2 + 0] = (float)i0;
        ido[gr * 2 + 1] = (float)i1;
    }
}

extern "C" void kernel_launch(void* const* d_in, const int* in_sizes, int n_in,
                              void* d_out, int out_size) {
    const float* x    = (const float*)d_in[0];
    const float* gw   = (const float*)d_in[1];
    const float* bias = (const float*)d_in[2];
    float* out = (float*)d_out;
    int n_rows = in_sizes[0] / D_MODEL;   // 32768
    int grid = n_rows / M_TILE;           // 512
    router_kernel<<<grid, NTHREADS>>>(x, gw, bias, out, n_rows);
}

// round 4
// speedup vs baseline: 1.8440x; 1.8440x over previous
#include <cuda_runtime.h>
#include <cuda_bf16.h>
#include <mma.h>
#include <cstdint>

using namespace nvcuda;

#define D_MODEL 2048
#define NUM_EXPERTS 64
#define M_TILE 128
#define KC 32
#define T_CHUNKS (D_MODEL / KC)   // 64
#define NTHREADS 256
#define AS 40                      // A row stride (bf16 elts), 80B
#define WS 40                      // B column stride (bf16 elts)
#define A_ELTS (M_TILE * AS)       // 5120
#define B_ELTS (NUM_EXPERTS * WS)  // 2560
#define SMEM_ELTS (3 * A_ELTS + 3 * B_ELTS)   // 23040 bf16 = 46080 B
#define LSTRIDE 72                 // logits row stride (floats)

__device__ __align__(16) __nv_bfloat16 g_w0[NUM_EXPERTS * D_MODEL];
__device__ __align__(16) __nv_bfloat16 g_w1[NUM_EXPERTS * D_MODEL];
__device__ __align__(16) __nv_bfloat16 g_w2[NUM_EXPERTS * D_MODEL];

// ---------------- W split precompute (runs once per launch; tiny) ----------------
__global__ void prep_w(const float* __restrict__ w) {
    int i = (blockIdx.x * blockDim.x + threadIdx.x) * 4;
    float4 v = *reinterpret_cast<const float4*>(w + i);
    float a[4] = {v.x, v.y, v.z, v.w};
#pragma unroll
    for (int j = 0; j < 4; j++) {
        float t = a[j];
        __nv_bfloat16 b0 = __float2bfloat16(t);
        float r = t - __bfloat162float(b0);
        __nv_bfloat16 b1 = __float2bfloat16(r);
        r = r - __bfloat162float(b1);
        __nv_bfloat16 b2 = __float2bfloat16(r);
        g_w0[i + j] = b0;
        g_w1[i + j] = b1;
        g_w2[i + j] = b2;
    }
}

// ---------------- main router kernel ----------------
__global__ void __launch_bounds__(NTHREADS) router_wmma(
    const float* __restrict__ x,
    const float* __restrict__ bias,
    float* __restrict__ out,
    int n_rows)
{
    __shared__ __align__(16) __nv_bfloat16 smem[SMEM_ELTS];

    __nv_bfloat16* A0 = smem;
    __nv_bfloat16* A1 = smem + A_ELTS;
    __nv_bfloat16* A2 = smem + 2 * A_ELTS;
    __nv_bfloat16* B0 = smem + 3 * A_ELTS;
    __nv_bfloat16* B1 = smem + 3 * A_ELTS + B_ELTS;
    __nv_bfloat16* B2 = smem + 3 * A_ELTS + 2 * B_ELTS;

    const int tid = threadIdx.x;
    const int wid = tid >> 5;
    const int wm = wid & 3;        // warp m-group: rows 32*wm .. 32*wm+31
    const int wn = wid >> 2;       // warp n-group: experts 32*wn .. 32*wn+31
    const long long row0 = (long long)blockIdx.x * M_TILE;

    // loader mapping
    const int xrow = tid >> 1;           // 0..127
    const int xcb  = (tid & 1) * 16;     // column base (floats)
    const int we   = tid >> 2;           // 0..63
    const int wkq  = (tid & 3) * 8;      // k offset within chunk

    const float* xb = x + row0 * D_MODEL;

    wmma::fragment<wmma::accumulator, 16, 16, 16, float> acc[2][2];
#pragma unroll
    for (int mt = 0; mt < 2; mt++)
#pragma unroll
        for (int nt = 0; nt < 2; nt++) wmma::fill_fragment(acc[mt][nt], 0.0f);

    float4 xv[4];
    uint4 wv[3];

    auto loadg = [&](int c) {
        const int k0 = c * KC;
        const float* xp = xb + (long long)xrow * D_MODEL + k0 + xcb;
#pragma unroll
        for (int i = 0; i < 4; i++)
            xv[i] = *reinterpret_cast<const float4*>(xp + 4 * i);
        const size_t wo = (size_t)we * D_MODEL + k0 + wkq;
        wv[0] = *reinterpret_cast<const uint4*>(g_w0 + wo);
        wv[1] = *reinterpret_cast<const uint4*>(g_w1 + wo);
        wv[2] = *reinterpret_cast<const uint4*>(g_w2 + wo);
    };

    auto stores = [&]() {
        // x: split into 3 bf16 levels
#pragma unroll
        for (int i = 0; i < 4; i++) {
            float a0 = xv[i].x, a1 = xv[i].y, a2 = xv[i].z, a3 = xv[i].w;
            __nv_bfloat162 h0a = __floats2bfloat162_rn(a0, a1);
            __nv_bfloat162 h0b = __floats2bfloat162_rn(a2, a3);
            float r0 = a0 - __bfloat162float(h0a.x);
            float r1 = a1 - __bfloat162float(h0a.y);
            float r2 = a2 - __bfloat162float(h0b.x);
            float r3 = a3 - __bfloat162float(h0b.y);
            __nv_bfloat162 h1a = __floats2bfloat162_rn(r0, r1);
            __nv_bfloat162 h1b = __floats2bfloat162_rn(r2, r3);
            r0 -= __bfloat162float(h1a.x);
            r1 -= __bfloat162float(h1a.y);
            r2 -= __bfloat162float(h1b.x);
            r3 -= __bfloat162float(h1b.y);
            __nv_bfloat162 h2a = __floats2bfloat162_rn(r0, r1);
            __nv_bfloat162 h2b = __floats2bfloat162_rn(r2, r3);

            const int o = xrow * AS + xcb + 4 * i;
            *reinterpret_cast<uint2*>(A0 + o) =
                make_uint2(*reinterpret_cast<uint32_t*>(&h0a), *reinterpret_cast<uint32_t*>(&h0b));
            *reinterpret_cast<uint2*>(A1 + o) =
                make_uint2(*reinterpret_cast<uint32_t*>(&h1a), *reinterpret_cast<uint32_t*>(&h1b));
            *reinterpret_cast<uint2*>(A2 + o) =
                make_uint2(*reinterpret_cast<uint32_t*>(&h2a), *reinterpret_cast<uint32_t*>(&h2b));
        }
        // W: already bf16
        const int bo = we * WS + wkq;
        *reinterpret_cast<uint4*>(B0 + bo) = wv[0];
        *reinterpret_cast<uint4*>(B1 + bo) = wv[1];
        *reinterpret_cast<uint4*>(B2 + bo) = wv[2];
    };

    auto compute = [&]() {
#pragma unroll
        for (int ks = 0; ks < KC; ks += 16) {
            wmma::fragment<wmma::matrix_a, 16, 16, 16, __nv_bfloat16, wmma::row_major> af0[2], af1[2], af2[2];
#pragma unroll
            for (int mt = 0; mt < 2; mt++) {
                const int ro = (32 * wm + 16 * mt) * AS + ks;
                wmma::load_matrix_sync(af0[mt], A0 + ro, AS);
                wmma::load_matrix_sync(af1[mt], A1 + ro, AS);
                wmma::load_matrix_sync(af2[mt], A2 + ro, AS);
            }
#pragma unroll
            for (int nt = 0; nt < 2; nt++) {
                wmma::fragment<wmma::matrix_b, 16, 16, 16, __nv_bfloat16, wmma::col_major> bf0, bf1, bf2;
                const int co = (32 * wn + 16 * nt) * WS + ks;
                wmma::load_matrix_sync(bf0, B0 + co, WS);
                wmma::load_matrix_sync(bf1, B1 + co, WS);
                wmma::load_matrix_sync(bf2, B2 + co, WS);
#pragma unroll
                for (int mt = 0; mt < 2; mt++) {
                    wmma::mma_sync(acc[mt][nt], af0[mt], bf0, acc[mt][nt]);
                    wmma::mma_sync(acc[mt][nt], af0[mt], bf1, acc[mt][nt]);
                    wmma::mma_sync(acc[mt][nt], af1[mt], bf0, acc[mt][nt]);
                    wmma::mma_sync(acc[mt][nt], af1[mt], bf1, acc[mt][nt]);
                    wmma::mma_sync(acc[mt][nt], af2[mt], bf0, acc[mt][nt]);
                    wmma::mma_sync(acc[mt][nt], af0[mt], bf2, acc[mt][nt]);
                }
            }
        }
    };

    // ---- pipelined main loop: gmem prefetch in regs, single smem buffer ----
    loadg(0);
    stores();
    __syncthreads();

#pragma unroll 1
    for (int c = 0; c < T_CHUNKS; ++c) {
        if (c + 1 < T_CHUNKS) loadg(c + 1);
        compute();
        __syncthreads();            // all warps done reading smem
        if (c + 1 < T_CHUNKS) {
            stores();
            __syncthreads();        // tiles for chunk c+1 visible
        }
    }

    // ---- epilogue: logits to smem (reuse tile memory) ----
    float* logits = reinterpret_cast<float*>(smem);
    __syncthreads();
#pragma unroll
    for (int mt = 0; mt < 2; mt++)
#pragma unroll
        for (int nt = 0; nt < 2; nt++)
            wmma::store_matrix_sync(
                logits + (32 * wm + 16 * mt) * LSTRIDE + 32 * wn + 16 * nt,
                acc[mt][nt], LSTRIDE, wmma::mem_row_major);
    __syncthreads();

    if (tid < M_TILE) {
        const int r = tid;
        const float* lrow = logits + r * LSTRIDE;
        float v0 = -3.0e38f, v1 = -3.0e38f;
        int i0 = 0, i1 = 0;
#pragma unroll
        for (int e = 0; e < NUM_EXPERTS; e++) {
            float l = lrow[e] + __ldg(&bias[e]);
            if (l > v0) { v1 = v0; i1 = i0; v0 = l; i0 = e; }
            else if (l > v1) { v1 = l; i1 = e; }
        }
        float Z = 0.0f;
#pragma unroll
        for (int e = 0; e < NUM_EXPERTS; e++) {
            float l = lrow[e] + __ldg(&bias[e]);
            Z += __expf(l - v0);
        }
        float q0 = 1.0f / Z;
        float q1 = __expf(v1 - v0) / Z;
        float s = q0 + q1 + 1e-8f;
        long long gr = row0 + r;
        out[gr * 2 + 0] = q0 / s;
        out[gr * 2 + 1] = q1 / s;
        float* ido = out + (long long)n_rows * 2;
        ido[gr * 2 + 0] = (float)i0;
        ido[gr * 2 + 1] = (float)i1;
    }
}

extern "C" void kernel_launch(void* const* d_in, const int* in_sizes, int n_in,
                              void* d_out, int out_size) {
    const float* x    = (const float*)d_in[0];
    const float* gw   = (const float*)d_in[1];
    const float* bias = (const float*)d_in[2];
    float* out = (float*)d_out;
    int n_rows = in_sizes[0] / D_MODEL;   // 32768

    prep_w<<<(NUM_EXPERTS * D_MODEL / 4) / 256, 256>>>(gw);
    router_wmma<<<n_rows / M_TILE, NTHREADS>>>(x, bias, out, n_rows);
}

// round 5
// speedup vs baseline: 3.3830x; 1.8346x over previous
#include <cuda_runtime.h>
#include <cuda_fp16.h>
#include <mma.h>
#include <cstdint>

using namespace nvcuda;

#define D_MODEL 2048
#define NUM_EXPERTS 64
#define M_TILE 128
#define KC 32
#define T_CHUNKS (D_MODEL / KC)    // 64
#define NTHREADS 256
#define AS 40                      // A row stride (halfs) = 80B
#define WS 40                      // B column stride (halfs)
#define A_ELTS (M_TILE * AS)       // 5120
#define B_ELTS (NUM_EXPERTS * WS)  // 2560
#define SBUF_ELTS (2 * A_ELTS + 2 * B_ELTS)   // 15360 halfs = 30720 B per stage
#define SMEM_BYTES (2 * SBUF_ELTS * 2)        // 61440 B
#define LSTRIDE 72                 // logits row stride (floats)

__device__ __align__(16) __half g_w0[NUM_EXPERTS * D_MODEL];
__device__ __align__(16) __half g_w1[NUM_EXPERTS * D_MODEL];

// ---------------- W split precompute (tiny, once per launch) ----------------
__global__ void prep_w(const float* __restrict__ w) {
    int i = (blockIdx.x * blockDim.x + threadIdx.x) * 4;
    float4 v = *reinterpret_cast<const float4*>(w + i);
    float a[4] = {v.x, v.y, v.z, v.w};
#pragma unroll
    for (int j = 0; j < 4; j++) {
        float t = a[j];
        __half h0 = __float2half_rn(t);
        float r = t - __half2float(h0);
        __half h1 = __float2half_rn(r);
        g_w0[i + j] = h0;
        g_w1[i + j] = h1;
    }
}

// ---------------- main router kernel ----------------
__global__ void __launch_bounds__(NTHREADS, 2) router_hsplit(
    const float* __restrict__ x,
    const float* __restrict__ bias,
    float* __restrict__ out,
    int n_rows)
{
    extern __shared__ __align__(16) __half smem[];

    const int tid = threadIdx.x;
    const int wid = tid >> 5;
    const int wm = wid & 3;        // warp m-group: rows 32*wm..32*wm+31
    const int wn = wid >> 2;       // warp n-group: experts 32*wn..32*wn+31
    const long long row0 = (long long)blockIdx.x * M_TILE;

    // loader mapping
    const int xrow = tid >> 1;           // 0..127
    const int xcb  = (tid & 1) * 16;     // x column base (floats)
    const int we   = tid >> 2;           // 0..63
    const int wq   = (tid & 3) * 8;      // k offset within chunk (halfs)

    const float* xb = x + row0 * D_MODEL;

    wmma::fragment<wmma::accumulator, 16, 16, 16, float> acc[2][2];
#pragma unroll
    for (int mt = 0; mt < 2; mt++)
#pragma unroll
        for (int nt = 0; nt < 2; nt++) wmma::fill_fragment(acc[mt][nt], 0.0f);

    float4 xv[4];
    uint4 wv[2];

    auto loadg = [&](int c) {
        const int k0 = c * KC;
        const float* xp = xb + (long long)xrow * D_MODEL + k0 + xcb;
#pragma unroll
        for (int i = 0; i < 4; i++)
            xv[i] = *reinterpret_cast<const float4*>(xp + 4 * i);
        const size_t wo = (size_t)we * D_MODEL + k0 + wq;
        wv[0] = *reinterpret_cast<const uint4*>(g_w0 + wo);
        wv[1] = *reinterpret_cast<const uint4*>(g_w1 + wo);
    };

    auto stores = [&](int buf) {
        __half* A0 = smem + buf * SBUF_ELTS;
        __half* A1 = A0 + A_ELTS;
        __half* B0 = A0 + 2 * A_ELTS;
        __half* B1 = B0 + B_ELTS;
#pragma unroll
        for (int i = 0; i < 4; i++) {
            float a0 = xv[i].x, a1 = xv[i].y, a2 = xv[i].z, a3 = xv[i].w;
            __half2 h0a = __floats2half2_rn(a0, a1);
            __half2 h0b = __floats2half2_rn(a2, a3);
            float r0 = a0 - __half2float(h0a.x);
            float r1 = a1 - __half2float(h0a.y);
            float r2 = a2 - __half2float(h0b.x);
            float r3 = a3 - __half2float(h0b.y);
            __half2 h1a = __floats2half2_rn(r0, r1);
            __half2 h1b = __floats2half2_rn(r2, r3);

            const int o = xrow * AS + xcb + 4 * i;
            *reinterpret_cast<uint2*>(A0 + o) =
                make_uint2(*reinterpret_cast<uint32_t*>(&h0a), *reinterpret_cast<uint32_t*>(&h0b));
            *reinterpret_cast<uint2*>(A1 + o) =
                make_uint2(*reinterpret_cast<uint32_t*>(&h1a), *reinterpret_cast<uint32_t*>(&h1b));
        }
        const int bo = we * WS + wq;
        *reinterpret_cast<uint4*>(B0 + bo) = wv[0];
        *reinterpret_cast<uint4*>(B1 + bo) = wv[1];
    };

    auto compute = [&](int buf) {
        const __half* A0 = smem + buf * SBUF_ELTS;
        const __half* A1 = A0 + A_ELTS;
        const __half* B0 = A0 + 2 * A_ELTS;
        const __half* B1 = B0 + B_ELTS;
#pragma unroll
        for (int ks = 0; ks < KC; ks += 16) {
            wmma::fragment<wmma::matrix_a, 16, 16, 16, __half, wmma::row_major> a0f[2], a1f[2];
            wmma::fragment<wmma::matrix_b, 16, 16, 16, __half, wmma::col_major> b0f[2], b1f[2];
#pragma unroll
            for (int mt = 0; mt < 2; mt++) {
                const int ro = (32 * wm + 16 * mt) * AS + ks;
                wmma::load_matrix_sync(a0f[mt], A0 + ro, AS);
                wmma::load_matrix_sync(a1f[mt], A1 + ro, AS);
            }
#pragma unroll
            for (int nt = 0; nt < 2; nt++) {
                const int co = (32 * wn + 16 * nt) * WS + ks;
                wmma::load_matrix_sync(b0f[nt], B0 + co, WS);
                wmma::load_matrix_sync(b1f[nt], B1 + co, WS);
            }
            // product-major order: same-acc dependency distance = 4 MMAs
#pragma unroll
            for (int mt = 0; mt < 2; mt++)
#pragma unroll
                for (int nt = 0; nt < 2; nt++)
                    wmma::mma_sync(acc[mt][nt], a0f[mt], b0f[nt], acc[mt][nt]);
#pragma unroll
            for (int mt = 0; mt < 2; mt++)
#pragma unroll
                for (int nt = 0; nt < 2; nt++)
                    wmma::mma_sync(acc[mt][nt], a0f[mt], b1f[nt], acc[mt][nt]);
#pragma unroll
            for (int mt = 0; mt < 2; mt++)
#pragma unroll
                for (int nt = 0; nt < 2; nt++)
                    wmma::mma_sync(acc[mt][nt], a1f[mt], b0f[nt], acc[mt][nt]);
        }
    };

    // ---- double-buffered main loop: 1 sync per chunk ----
    loadg(0);
    stores(0);
    __syncthreads();

#pragma unroll 1
    for (int c = 0; c < T_CHUNKS; ++c) {
        if (c + 1 < T_CHUNKS) loadg(c + 1);
        compute(c & 1);
        if (c + 1 < T_CHUNKS) stores((c + 1) & 1);
        __syncthreads();
    }

    // ---- epilogue ----
    float* logits = reinterpret_cast<float*>(smem);
#pragma unroll
    for (int mt = 0; mt < 2; mt++)
#pragma unroll
        for (int nt = 0; nt < 2; nt++)
            wmma::store_matrix_sync(
                logits + (32 * wm + 16 * mt) * LSTRIDE + 32 * wn + 16 * nt,
                acc[mt][nt], LSTRIDE, wmma::mem_row_major);
    __syncthreads();

    if (tid < M_TILE) {
        const int r = tid;
        const float* lrow = logits + r * LSTRIDE;
        float v0 = -3.0e38f, v1 = -3.0e38f;
        int i0 = 0, i1 = 0;
#pragma unroll
        for (int e = 0; e < NUM_EXPERTS; e++) {
            float l = lrow[e] + __ldg(&bias[e]);
            if (l > v0) { v1 = v0; i1 = i0; v0 = l; i0 = e; }
            else if (l > v1) { v1 = l; i1 = e; }
        }
        float Z = 0.0f;
#pragma unroll
        for (int e = 0; e < NUM_EXPERTS; e++) {
            float l = lrow[e] + __ldg(&bias[e]);
            Z += __expf(l - v0);
        }
        float q0 = 1.0f / Z;
        float q1 = __expf(v1 - v0) / Z;
        float s = q0 + q1 + 1e-8f;
        long long gr = row0 + r;
        out[gr * 2 + 0] = q0 / s;
        out[gr * 2 + 1] = q1 / s;
        float* ido = out + (long long)n_rows * 2;
        ido[gr * 2 + 0] = (float)i0;
        ido[gr * 2 + 1] = (float)i1;
    }
}

extern "C" void kernel_launch(void* const* d_in, const int* in_sizes, int n_in,
                              void* d_out, int out_size) {
    const float* x    = (const float*)d_in[0];
    const float* gw   = (const float*)d_in[1];
    const float* bias = (const float*)d_in[2];
    float* out = (float*)d_out;
    int n_rows = in_sizes[0] / D_MODEL;   // 32768

    cudaFuncSetAttribute(router_hsplit, cudaFuncAttributeMaxDynamicSharedMemorySize, SMEM_BYTES);

    prep_w<<<(NUM_EXPERTS * D_MODEL / 4) / 256, 256>>>(gw);
    router_hsplit<<<n_rows / M_TILE, NTHREADS, SMEM_BYTES>>>(x, bias, out, n_rows);
}

// round 6
// speedup vs baseline: 4.0781x; 1.2055x over previous
#include <cuda_runtime.h>
#include <cuda_fp16.h>
#include <mma.h>
#include <cstdint>

using namespace nvcuda;

#define D_MODEL 2048
#define NUM_EXPERTS 64
#define M_TILE 128
#define KC 32
#define T_CHUNKS (D_MODEL / KC)    // 64
#define NTHREADS 256
#define AS 40                      // A row stride (halfs) = 80B
#define WS 40                      // B row stride (halfs)
#define A_ELTS (M_TILE * AS)       // 5120
#define B_ELTS (NUM_EXPERTS * WS)  // 2560
#define SBUF_ELTS (2 * A_ELTS + 2 * B_ELTS)   // 15360 halfs
#define SMEM_BYTES (2 * SBUF_ELTS * 2)        // 61440 B
#define LSTRIDE 72                 // logits row stride (floats)

// W pre-packed chunk-contiguous: [chunk][lev][e][32 halfs]
__device__ __align__(16) __half g_wp[2 * NUM_EXPERTS * D_MODEL];

// ---------------- W split + repack precompute (tiny, once per launch) ----------------
__global__ void prep_w(const float* __restrict__ w) {
    int i = (blockIdx.x * blockDim.x + threadIdx.x) * 4;   // over E*D elements
    float4 v = *reinterpret_cast<const float4*>(w + i);
    float a[4] = {v.x, v.y, v.z, v.w};
    __half h0[4], h1[4];
#pragma unroll
    for (int j = 0; j < 4; j++) {
        __half t0 = __float2half_rn(a[j]);
        h0[j] = t0;
        h1[j] = __float2half_rn(a[j] - __half2float(t0));
    }
    const int e = i / D_MODEL;
    const int k = i % D_MODEL;
    const int c = k >> 5;
    const int kk = k & 31;
    // dst base (halfs): ((c*2 + lev) * 64 + e) * 32 + kk
    __half* d0 = g_wp + ((size_t)(c * 2 + 0) * 64 + e) * 32 + kk;
    __half* d1 = g_wp + ((size_t)(c * 2 + 1) * 64 + e) * 32 + kk;
    *reinterpret_cast<uint2*>(d0) = *reinterpret_cast<uint2*>(h0);
    *reinterpret_cast<uint2*>(d1) = *reinterpret_cast<uint2*>(h1);
}

// ---------------- main router kernel ----------------
__global__ void __launch_bounds__(NTHREADS, 2) router_hsplit(
    const float* __restrict__ x,
    const float* __restrict__ bias,
    float* __restrict__ out,
    int n_rows)
{
    extern __shared__ __align__(16) __half smem[];

    const int tid = threadIdx.x;
    const int wid = tid >> 5;
    const int wm = wid & 3;        // warp m-group
    const int wn = wid >> 2;       // warp n-group
    const long long row0 = (long long)blockIdx.x * M_TILE;

    // coalesced x loader: 8 lanes cover one 128B line
    const int xr  = tid >> 3;            // base row 0..31 (sweeps add +32)
    const int xc4 = (tid & 7) * 4;       // float col
    // W loader: dense block
    const int we2 = tid >> 2;            // expert 0..63
    const int wk2 = (tid & 3) * 8;       // k offset (halfs)

    const float* xb = x + row0 * D_MODEL;

    wmma::fragment<wmma::accumulator, 16, 16, 16, float> acc[2][2];
#pragma unroll
    for (int mt = 0; mt < 2; mt++)
#pragma unroll
        for (int nt = 0; nt < 2; nt++) wmma::fill_fragment(acc[mt][nt], 0.0f);

    float4 xv[4];
    uint4 wv[2];

    auto loadg = [&](int c) {
        const int k0 = c * KC;
#pragma unroll
        for (int i = 0; i < 4; i++)
            xv[i] = *reinterpret_cast<const float4*>(
                xb + (long long)(xr + 32 * i) * D_MODEL + k0 + xc4);
        const __half* wbase = g_wp + (size_t)c * 2 * NUM_EXPERTS * KC;  // c*4096 halfs
        wv[0] = *reinterpret_cast<const uint4*>(wbase + tid * 8);
        wv[1] = *reinterpret_cast<const uint4*>(wbase + 2048 + tid * 8);
    };

    auto stores = [&](int buf) {
        __half* A0 = smem + buf * SBUF_ELTS;
        __half* A1 = A0 + A_ELTS;
        __half* B0 = A0 + 2 * A_ELTS;
        __half* B1 = B0 + B_ELTS;
#pragma unroll
        for (int i = 0; i < 4; i++) {
            float a0 = xv[i].x, a1 = xv[i].y, a2 = xv[i].z, a3 = xv[i].w;
            __half2 h0a = __floats2half2_rn(a0, a1);
            __half2 h0b = __floats2half2_rn(a2, a3);
            float r0 = a0 - __half2float(h0a.x);
            float r1 = a1 - __half2float(h0a.y);
            float r2 = a2 - __half2float(h0b.x);
            float r3 = a3 - __half2float(h0b.y);
            __half2 h1a = __floats2half2_rn(r0, r1);
            __half2 h1b = __floats2half2_rn(r2, r3);

            const int o = (xr + 32 * i) * AS + xc4;
            *reinterpret_cast<uint2*>(A0 + o) =
                make_uint2(*reinterpret_cast<uint32_t*>(&h0a), *reinterpret_cast<uint32_t*>(&h0b));
            *reinterpret_cast<uint2*>(A1 + o) =
                make_uint2(*reinterpret_cast<uint32_t*>(&h1a), *reinterpret_cast<uint32_t*>(&h1b));
        }
        const int bo = we2 * WS + wk2;
        *reinterpret_cast<uint4*>(B0 + bo) = wv[0];
        *reinterpret_cast<uint4*>(B1 + bo) = wv[1];
    };

    auto compute = [&](int buf) {
        const __half* A0 = smem + buf * SBUF_ELTS;
        const __half* A1 = A0 + A_ELTS;
        const __half* B0 = A0 + 2 * A_ELTS;
        const __half* B1 = B0 + B_ELTS;
#pragma unroll
        for (int ks = 0; ks < KC; ks += 16) {
            wmma::fragment<wmma::matrix_a, 16, 16, 16, __half, wmma::row_major> a0f[2], a1f[2];
            wmma::fragment<wmma::matrix_b, 16, 16, 16, __half, wmma::col_major> b0f[2], b1f[2];
#pragma unroll
            for (int mt = 0; mt < 2; mt++) {
                const int ro = (32 * wm + 16 * mt) * AS + ks;
                wmma::load_matrix_sync(a0f[mt], A0 + ro, AS);
                wmma::load_matrix_sync(a1f[mt], A1 + ro, AS);
            }
#pragma unroll
            for (int nt = 0; nt < 2; nt++) {
                const int co = (32 * wn + 16 * nt) * WS + ks;
                wmma::load_matrix_sync(b0f[nt], B0 + co, WS);
                wmma::load_matrix_sync(b1f[nt], B1 + co, WS);
            }
#pragma unroll
            for (int mt = 0; mt < 2; mt++)
#pragma unroll
                for (int nt = 0; nt < 2; nt++)
                    wmma::mma_sync(acc[mt][nt], a0f[mt], b0f[nt], acc[mt][nt]);
#pragma unroll
            for (int mt = 0; mt < 2; mt++)
#pragma unroll
                for (int nt = 0; nt < 2; nt++)
                    wmma::mma_sync(acc[mt][nt], a0f[mt], b1f[nt], acc[mt][nt]);
#pragma unroll
            for (int mt = 0; mt < 2; mt++)
#pragma unroll
                for (int nt = 0; nt < 2; nt++)
                    wmma::mma_sync(acc[mt][nt], a1f[mt], b0f[nt], acc[mt][nt]);
        }
    };

    // ---- double-buffered main loop ----
    loadg(0);
    stores(0);
    __syncthreads();

#pragma unroll 1
    for (int c = 0; c < T_CHUNKS; ++c) {
        if (c + 1 < T_CHUNKS) loadg(c + 1);
        compute(c & 1);
        if (c + 1 < T_CHUNKS) stores((c + 1) & 1);
        __syncthreads();
    }

    // ---- epilogue ----
    float* logits = reinterpret_cast<float*>(smem);
#pragma unroll
    for (int mt = 0; mt < 2; mt++)
#pragma unroll
        for (int nt = 0; nt < 2; nt++)
            wmma::store_matrix_sync(
                logits + (32 * wm + 16 * mt) * LSTRIDE + 32 * wn + 16 * nt,
                acc[mt][nt], LSTRIDE, wmma::mem_row_major);
    __syncthreads();

    if (tid < M_TILE) {
        const int r = tid;
        const float* lrow = logits + r * LSTRIDE;
        float v0 = -3.0e38f, v1 = -3.0e38f;
        int i0 = 0, i1 = 0;
#pragma unroll
        for (int e = 0; e < NUM_EXPERTS; e++) {
            float l = lrow[e] + __ldg(&bias[e]);
            if (l > v0) { v1 = v0; i1 = i0; v0 = l; i0 = e; }
            else if (l > v1) { v1 = l; i1 = e; }
        }
        float Z = 0.0f;
#pragma unroll
        for (int e = 0; e < NUM_EXPERTS; e++) {
            float l = lrow[e] + __ldg(&bias[e]);
            Z += __expf(l - v0);
        }
        float q0 = 1.0f / Z;
        float q1 = __expf(v1 - v0) / Z;
        float s = q0 + q1 + 1e-8f;
        long long gr = row0 + r;
        out[gr * 2 + 0] = q0 / s;
        out[gr * 2 + 1] = q1 / s;
        float* ido = out + (long long)n_rows * 2;
        ido[gr * 2 + 0] = (float)i0;
        ido[gr * 2 + 1] = (float)i1;
    }
}

extern "C" void kernel_launch(void* const* d_in, const int* in_sizes, int n_in,
                              void* d_out, int out_size) {
    const float* x    = (const float*)d_in[0];
    const float* gw   = (const float*)d_in[1];
    const float* bias = (const float*)d_in[2];
    float* out = (float*)d_out;
    int n_rows = in_sizes[0] / D_MODEL;   // 32768

    cudaFuncSetAttribute(router_hsplit, cudaFuncAttributeMaxDynamicSharedMemorySize, SMEM_BYTES);

    prep_w<<<(NUM_EXPERTS * D_MODEL / 4) / 256, 256>>>(gw);
    router_hsplit<<<n_rows / M_TILE, NTHREADS, SMEM_BYTES>>>(x, bias, out, n_rows);
}